// round 2
// baseline (speedup 1.0000x reference)
#include <cuda_runtime.h>
#include <cstddef>

// FISM scoring kernel.
//   B=16384 rows, K=50 neighbors/row (contiguous slice of I_U), NNEG=20, D=128.
// Inputs (metadata order):
//   0:I int32[B] 1:U int32[B] 2:I_neg int32[B,NNEG] 3:I_U int32[B*K]
//   4:N_U int32[B] 5:I_in_I_U int32[B]
//   6:P_emb f32[N_ITEMS,D] 7:Q_emb f32[N_ITEMS,D] 8:b_u f32[N_USERS] 9:b_i f32[N_ITEMS]
// Output: concat(r [B], r_neg [B*NNEG]) f32.
//
// NOTE: harness input pointers are only 4-byte aligned -> no float4 loads
// from global memory. All global access is scalar & coalesced.

#define FB    16384
#define FK    50
#define FNNEG 20
#define FD    128

__global__ __launch_bounds__(128, 8) void fism_kernel(
    const int*   __restrict__ I,
    const int*   __restrict__ U,
    const int*   __restrict__ I_neg,
    const int*   __restrict__ I_U,
    const int*   __restrict__ N_U,
    const int*   __restrict__ I_in,
    const float* __restrict__ P,
    const float* __restrict__ Q,
    const float* __restrict__ b_u,
    const float* __restrict__ b_i,
    float*       __restrict__ out)
{
    const int b   = blockIdx.x;
    const int tid = threadIdx.x;              // 0..127, owns dim `tid`

    __shared__ int   s_idx[FK];
    __shared__ float s_p[FD];
    __shared__ int   s_scalars[4];            // I[b], U[b], N_U[b], I_in[b]

    if (tid < FK)  s_idx[tid] = I_U[(size_t)b * FK + tid];
    if (tid < 4) {
        const int* srcs[4] = {I, U, N_U, I_in};
        s_scalars[tid] = srcs[tid][b];
    }
    __syncthreads();

    const int   i_pos = s_scalars[0];
    const int   u     = s_scalars[1];
    const float n_u   = (float)s_scalars[2];
    const float ind   = (float)s_scalars[3];

    // ---- neighbor sum: 50 coalesced row gathers, full unroll for MLP ----
    float sum = 0.0f;
    #pragma unroll
    for (int k = 0; k < FK; k++) {
        sum += __ldg(&P[(size_t)s_idx[k] * FD + tid]);
    }
    sum -= __ldg(&P[(size_t)i_pos * FD + tid]) * ind;   // exclude self

    const float div = fmaxf(n_u - ind, 1.0f);           // ALPHA = 1
    s_p[tid] = sum / div;                               // p_ctx_avg[dim=tid]
    __syncthreads();

    // ---- 21 dot products (1 pos + 20 neg), 4 warps round-robin ----
    const int lane = tid & 31;
    const int warp = tid >> 5;

    // lane owns dims {lane, lane+32, lane+64, lane+96}
    const float p0 = s_p[lane];
    const float p1 = s_p[lane + 32];
    const float p2 = s_p[lane + 64];
    const float p3 = s_p[lane + 96];
    const float bu = __ldg(&b_u[u]);

    for (int t = warp; t < 1 + FNNEG; t += 4) {
        const int item = (t == 0) ? i_pos
                                  : __ldg(&I_neg[(size_t)b * FNNEG + (t - 1)]);
        const float* qr = Q + (size_t)item * FD;
        float d = p0 * __ldg(&qr[lane])
                + p1 * __ldg(&qr[lane + 32])
                + p2 * __ldg(&qr[lane + 64])
                + p3 * __ldg(&qr[lane + 96]);
        #pragma unroll
        for (int off = 16; off > 0; off >>= 1)
            d += __shfl_down_sync(0xffffffffu, d, off);
        if (lane == 0) {
            const float val = bu + __ldg(&b_i[item]) + d;
            if (t == 0) out[b] = val;                                 // r
            else        out[FB + (size_t)b * FNNEG + (t - 1)] = val;  // r_neg
        }
    }
}

extern "C" void kernel_launch(void* const* d_in, const int* in_sizes, int n_in,
                              void* d_out, int out_size)
{
    const int*   I     = (const int*)  d_in[0];
    const int*   U     = (const int*)  d_in[1];
    const int*   I_neg = (const int*)  d_in[2];
    const int*   I_U   = (const int*)  d_in[3];
    const int*   N_U   = (const int*)  d_in[4];
    const int*   I_in  = (const int*)  d_in[5];
    const float* P     = (const float*)d_in[6];
    const float* Q     = (const float*)d_in[7];
    const float* b_u   = (const float*)d_in[8];
    const float* b_i   = (const float*)d_in[9];
    float* out = (float*)d_out;

    fism_kernel<<<FB, 128>>>(I, U, I_neg, I_U, N_U, I_in, P, Q, b_u, b_i, out);
}

// round 3
// speedup vs baseline: 1.9652x; 1.9652x over previous
#include <cuda_runtime.h>
#include <cstddef>
#include <cstdint>

// FISM scoring: B=16384 rows, K=50 neighbors (contiguous in I_U), NNEG=20, D=128.
// Warp-per-row layout: no block barriers, p_ctx_avg lives in registers.
// Vectorized (float4) kernel dispatched when P and Q are 16B-aligned
// (input sizes are all 256B multiples so this is expected); scalar fallback
// otherwise. NOTE: R1's "misaligned address" was a shared-memory float4 cast,
// not the global pointers.

#define FB    16384
#define FK    50
#define FNNEG 20
#define FD    128
#define WPB   8          // warps (rows) per block

template<bool VEC>
__global__ __launch_bounds__(256, 4) void fism_warp(
    const int*   __restrict__ I,
    const int*   __restrict__ U,
    const int*   __restrict__ I_neg,
    const int*   __restrict__ I_U,
    const int*   __restrict__ N_U,
    const int*   __restrict__ I_in,
    const float* __restrict__ P,
    const float* __restrict__ Q,
    const float* __restrict__ b_u,
    const float* __restrict__ b_i,
    float*       __restrict__ out)
{
    const int wid  = threadIdx.x >> 5;
    const int lane = threadIdx.x & 31;
    const int b    = blockIdx.x * WPB + wid;     // FB = 2048 * 8, exact

    __shared__ int s_idx[WPB][FK];

    // stage this row's 50 neighbor indices (two coalesced loads)
    {
        const int* src = I_U + (size_t)b * FK;
        if (lane < 32)      s_idx[wid][lane]      = src[lane];
        if (lane < FK - 32) s_idx[wid][32 + lane] = src[32 + lane];
    }
    __syncwarp();

    const int   i_pos = __ldg(&I[b]);
    const int   u     = __ldg(&U[b]);
    const float ind   = (float)__ldg(&I_in[b]);
    const float n_u   = (float)__ldg(&N_U[b]);

    // ---- neighbor gather + sum -------------------------------------------
    // VEC:   lane owns dims [4*lane .. 4*lane+3]
    // !VEC:  lane owns dims {lane, lane+32, lane+64, lane+96}
    float a0 = 0.f, a1 = 0.f, a2 = 0.f, a3 = 0.f;
    #pragma unroll
    for (int k = 0; k < FK; k++) {
        const float* row = P + (size_t)s_idx[wid][k] * FD;
        if (VEC) {
            const float4 v = __ldg(reinterpret_cast<const float4*>(row) + lane);
            a0 += v.x; a1 += v.y; a2 += v.z; a3 += v.w;
        } else {
            a0 += __ldg(&row[lane]);
            a1 += __ldg(&row[lane + 32]);
            a2 += __ldg(&row[lane + 64]);
            a3 += __ldg(&row[lane + 96]);
        }
    }

    // exclude self if present
    {
        const float* row = P + (size_t)i_pos * FD;
        if (VEC) {
            const float4 v = __ldg(reinterpret_cast<const float4*>(row) + lane);
            a0 -= v.x * ind; a1 -= v.y * ind; a2 -= v.z * ind; a3 -= v.w * ind;
        } else {
            a0 -= __ldg(&row[lane])      * ind;
            a1 -= __ldg(&row[lane + 32]) * ind;
            a2 -= __ldg(&row[lane + 64]) * ind;
            a3 -= __ldg(&row[lane + 96]) * ind;
        }
    }

    const float inv = 1.0f / fmaxf(n_u - ind, 1.0f);   // ALPHA = 1
    const float p0 = a0 * inv, p1 = a1 * inv, p2 = a2 * inv, p3 = a3 * inv;

    // ---- 21 dot products (1 pos + 20 neg) --------------------------------
    const int   negi = (lane < FNNEG) ? __ldg(&I_neg[(size_t)b * FNNEG + lane]) : 0;
    const float bu   = __ldg(&b_u[u]);

    #pragma unroll
    for (int t = 0; t < 1 + FNNEG; t++) {
        const int item = (t == 0) ? i_pos
                                  : __shfl_sync(0xffffffffu, negi, t - 1);
        const float* qr = Q + (size_t)item * FD;
        float d;
        if (VEC) {
            const float4 v = __ldg(reinterpret_cast<const float4*>(qr) + lane);
            d = p0 * v.x + p1 * v.y + p2 * v.z + p3 * v.w;
        } else {
            d = p0 * __ldg(&qr[lane])
              + p1 * __ldg(&qr[lane + 32])
              + p2 * __ldg(&qr[lane + 64])
              + p3 * __ldg(&qr[lane + 96]);
        }
        #pragma unroll
        for (int off = 16; off > 0; off >>= 1)
            d += __shfl_down_sync(0xffffffffu, d, off);
        if (lane == 0) {
            const float val = bu + __ldg(&b_i[item]) + d;
            if (t == 0) out[b] = val;                                 // r
            else        out[FB + (size_t)b * FNNEG + (t - 1)] = val;  // r_neg
        }
    }
}

extern "C" void kernel_launch(void* const* d_in, const int* in_sizes, int n_in,
                              void* d_out, int out_size)
{
    const int*   I     = (const int*)  d_in[0];
    const int*   U     = (const int*)  d_in[1];
    const int*   I_neg = (const int*)  d_in[2];
    const int*   I_U   = (const int*)  d_in[3];
    const int*   N_U   = (const int*)  d_in[4];
    const int*   I_in  = (const int*)  d_in[5];
    const float* P     = (const float*)d_in[6];
    const float* Q     = (const float*)d_in[7];
    const float* b_u   = (const float*)d_in[8];
    const float* b_i   = (const float*)d_in[9];
    float* out = (float*)d_out;

    const bool aligned = (((uintptr_t)P & 15u) == 0) && (((uintptr_t)Q & 15u) == 0);

    dim3 grid(FB / WPB), block(32 * WPB);
    if (aligned)
        fism_warp<true ><<<grid, block>>>(I, U, I_neg, I_U, N_U, I_in, P, Q, b_u, b_i, out);
    else
        fism_warp<false><<<grid, block>>>(I, U, I_neg, I_U, N_U, I_in, P, Q, b_u, b_i, out);
}